// round 9
// baseline (speedup 1.0000x reference)
#include <cuda_runtime.h>
#include <cuda_bf16.h>
#include <cstdint>
#include <math.h>

// ---------------------------------------------------------------------------
// Fixed problem shape:
//   BATCH=2, SEQLEN=1024, D_MODEL=1024, D_INNER=2048, DT_RANK=128, D_STATE=16,
//   D_CONV=4. Tokens NT = 2048.
// ---------------------------------------------------------------------------
#define DI      2048
#define DM      1024
#define LSEQ    1024
#define NT      2048
#define NSTATE  16
#define DTR     128
#define XPN     160      // DT_RANK + 2*D_STATE

// ----------------------- device scratch (no mallocs) -----------------------
__device__ float g_xz   [NT * 2 * DI];      // in_proj out: [x_in | z]
__device__ float g_u    [NT * DI];          // silu(conv(x_in))
__device__ float g_xdbl [NT * XPN];         // u @ W_xproj
__device__ float g_dt   [NT * DI];          // softplus(...)
__device__ float g_ys   [NT * DI];          // gated scan output
__device__ float g_A    [DI * NSTATE];      // A = -exp(A_log)
__device__ float g_pxd  [8 * NT * XPN];     // split-K partials (xproj)
__device__ float g_pout [2 * NT * DM];      // split-K partials (out)

// ----------------------- misc device helpers -------------------------------
__device__ __forceinline__ float softplus_f(float x) {
    if (x > 20.0f) return x;
    return log1pf(__expf(x));
}

// ----------------------- packed f32x2 helpers (SIMT GEMM) ------------------
__device__ __forceinline__ unsigned long long dup2(float v) {
    unsigned long long r;
    asm("mov.b64 %0, {%1, %1};" : "=l"(r) : "f"(v));
    return r;
}
__device__ __forceinline__ void fma2(unsigned long long& a,
                                     unsigned long long x,
                                     unsigned long long y) {
    asm("fma.rn.f32x2 %0, %1, %2, %0;" : "+l"(a) : "l"(x), "l"(y));
}
__device__ __forceinline__ void upk2(unsigned long long v, float& lo, float& hi) {
    asm("mov.b64 {%0, %1}, %2;" : "=f"(lo), "=f"(hi) : "l"(v));
}

// ----------------------- tf32 tensor helpers -------------------------------
__device__ __forceinline__ void split_tf32(float v, unsigned& hi, unsigned& lo) {
    unsigned h;
    asm("cvt.rna.tf32.f32 %0, %1;" : "=r"(h) : "f"(v));
    float r = v - __uint_as_float(h);
    unsigned l;
    asm("cvt.rna.tf32.f32 %0, %1;" : "=r"(l) : "f"(r));
    hi = h; lo = l;
}
__device__ __forceinline__ void mma_tf32(float* d, const unsigned* a, const unsigned* b) {
    asm volatile(
        "mma.sync.aligned.m16n8k8.row.col.f32.tf32.tf32.f32 "
        "{%0,%1,%2,%3}, {%4,%5,%6,%7}, {%8,%9}, {%0,%1,%2,%3};\n"
        : "+f"(d[0]), "+f"(d[1]), "+f"(d[2]), "+f"(d[3])
        : "r"(a[0]), "r"(a[1]), "r"(a[2]), "r"(a[3]), "r"(b[0]), "r"(b[1]));
}

// ---------------------------------------------------------------------------
// Tensor-core tf32 GEMM with 3-term precision compensation.
//   C[M,N] = A[M,K] @ B[K,N], row-major, fp32 in/out, rel err ~1e-7.
//   128x128 block tile, BK=16, 256 threads = 8 warps (4x2), warp = 32x64.
//   Requires: M%128==0, N%128==0, Kslice%16==0.
//   EPI==1 -> softplus(acc + bias[col]).
//   blockIdx.z = split-K slice, writes C + bz*cSliceStride.
// ---------------------------------------------------------------------------
template <int EPI>
__global__ void __launch_bounds__(256)
tgemm_tf32(const float* __restrict__ A, const float* __restrict__ B,
           float* __restrict__ C, int M, int N, int K,
           int lda, int ldb, int ldc,
           int Kslice, long long cSliceStride, const float* __restrict__ bias)
{
    // padded layouts: A stride 20 (bank=(20r+c)%32 hits all banks),
    //                 B stride 136 (bank=(8c+n)%32 hits all banks)
    __shared__ __align__(16) float As[2][128 * 20];
    __shared__ __align__(16) float Bs[2][16 * 136];

    const int tid  = threadIdx.x;
    const int lane = tid & 31;
    const int wid  = tid >> 5;
    const int wm   = wid & 3;        // 4 warps in M
    const int wn   = wid >> 2;       // 2 warps in N
    const int bx = blockIdx.x, by = blockIdx.y, bz = blockIdx.z;

    C += (long long)bz * cSliceStride;
    const int k0 = bz * Kslice;
    const int KT = Kslice >> 4;      // k-tiles of 16

    // global load mapping: A 128x16 (2 float4/thread), B 16x128 (2 float4/thread)
    const int aRow = tid >> 1;
    const int aK   = (tid & 1) * 8;
    const int bRow = tid >> 4;
    const int bCol = (tid & 15) * 8;

    const float* Ag = A + (long long)(by * 128 + aRow) * lda + k0 + aK;
    const float* Bg = B + (long long)(k0 + bRow) * ldb + bx * 128 + bCol;

    float acc[2][8][4];
#pragma unroll
    for (int mt = 0; mt < 2; mt++)
#pragma unroll
        for (int nt = 0; nt < 8; nt++)
#pragma unroll
            for (int j = 0; j < 4; j++) acc[mt][nt][j] = 0.f;

    // preload tile 0 into smem buffer 0
    {
        float4 pa0 = *(const float4*)(Ag);
        float4 pa1 = *(const float4*)(Ag + 4);
        float4 pb0 = *(const float4*)(Bg);
        float4 pb1 = *(const float4*)(Bg + 4);
        float* as = &As[0][aRow * 20 + aK];
        *(float4*)as = pa0; *(float4*)(as + 4) = pa1;
        float* bsw = &Bs[0][bRow * 136 + bCol];
        *(float4*)bsw = pb0; *(float4*)(bsw + 4) = pb1;
    }

    int cur = 0;
    const int frow = lane >> 2;      // 0..7
    const int fcol = lane & 3;       // 0..3

    for (int kt = 0; kt < KT; ++kt) {
        __syncthreads();

        float4 pa0, pa1, pb0, pb1;
        const bool more = (kt + 1 < KT);
        if (more) {
            const float* Ag2 = Ag + (kt + 1) * 16;
            const float* Bg2 = Bg + (long long)(kt + 1) * 16 * ldb;
            pa0 = *(const float4*)(Ag2);
            pa1 = *(const float4*)(Ag2 + 4);
            pb0 = *(const float4*)(Bg2);
            pb1 = *(const float4*)(Bg2 + 4);
        }

        const float* as = As[cur];
        const float* bs = Bs[cur];
#pragma unroll
        for (int ks = 0; ks < 2; ++ks) {
            const int c = ks * 8 + fcol;
            unsigned ah[2][4], al[2][4];
#pragma unroll
            for (int mt = 0; mt < 2; mt++) {
                const int r = wm * 32 + mt * 16 + frow;
                split_tf32(as[r * 20 + c],           ah[mt][0], al[mt][0]);
                split_tf32(as[(r + 8) * 20 + c],     ah[mt][1], al[mt][1]);
                split_tf32(as[r * 20 + c + 4],       ah[mt][2], al[mt][2]);
                split_tf32(as[(r + 8) * 20 + c + 4], ah[mt][3], al[mt][3]);
            }
#pragma unroll
            for (int nt = 0; nt < 8; nt++) {
                const int col = wn * 64 + nt * 8 + frow;
                unsigned bh[2], bl[2];
                split_tf32(bs[c * 136 + col],       bh[0], bl[0]);
                split_tf32(bs[(c + 4) * 136 + col], bh[1], bl[1]);
#pragma unroll
                for (int mt = 0; mt < 2; mt++) {
                    mma_tf32(acc[mt][nt], ah[mt], bh);   // hi*hi
                    mma_tf32(acc[mt][nt], al[mt], bh);   // lo*hi
                    mma_tf32(acc[mt][nt], ah[mt], bl);   // hi*lo
                }
            }
        }

        if (more) {
            float* asw = &As[cur ^ 1][aRow * 20 + aK];
            *(float4*)asw = pa0; *(float4*)(asw + 4) = pa1;
            float* bsw = &Bs[cur ^ 1][bRow * 136 + bCol];
            *(float4*)bsw = pb0; *(float4*)(bsw + 4) = pb1;
            cur ^= 1;
        }
    }

    // epilogue
    const int rbase = by * 128 + wm * 32;
    const int cbase = bx * 128 + wn * 64;
#pragma unroll
    for (int mt = 0; mt < 2; mt++) {
#pragma unroll
        for (int nt = 0; nt < 8; nt++) {
            const int r  = rbase + mt * 16 + frow;
            const int cc = cbase + nt * 8 + fcol * 2;
            float v0 = acc[mt][nt][0], v1 = acc[mt][nt][1];
            float v2 = acc[mt][nt][2], v3 = acc[mt][nt][3];
            if (EPI == 1) {
                const float b0 = bias[cc], b1 = bias[cc + 1];
                v0 = softplus_f(v0 + b0); v1 = softplus_f(v1 + b1);
                v2 = softplus_f(v2 + b0); v3 = softplus_f(v3 + b1);
            }
            *(float2*)&C[(long long)r * ldc + cc]       = make_float2(v0, v1);
            *(float2*)&C[(long long)(r + 8) * ldc + cc] = make_float2(v2, v3);
        }
    }
}

// ---------------------------------------------------------------------------
// SIMT fp32 GEMM (f32x2) — kept for xproj (N=160 not a multiple of 128).
// ---------------------------------------------------------------------------
__global__ void __launch_bounds__(256)
sgemm128(const float* __restrict__ A, const float* __restrict__ B,
         float* __restrict__ C, int M, int N, int K,
         int lda, int ldb, int ldc,
         int Kslice, long long cSliceStride)
{
    __shared__ __align__(16) float As[8][128];
    __shared__ __align__(16) float Bs[8][128];

    const int tid = threadIdx.x;
    const int bx = blockIdx.x, by = blockIdx.y, bz = blockIdx.z;
    C += (long long)bz * cSliceStride;
    const int k0base = bz * Kslice;
    const int kend   = min(K, k0base + Kslice);

    const int aRow = tid >> 1;
    const int aCol = (tid & 1) << 2;
    const int bRow = tid >> 5;
    const int bCol = (tid & 31) << 2;
    const int tx   = tid & 15;
    const int ty   = tid >> 4;

    const int  gBCol = bx * 128 + bCol;
    const bool bOk   = (gBCol < N);

    const float* Aptr = A + (long long)(by * 128 + aRow) * lda + aCol;
    const float* Bptr = B + gBCol;

    unsigned long long acc[8][4];
#pragma unroll
    for (int i = 0; i < 8; i++)
#pragma unroll
        for (int j = 0; j < 4; j++) acc[i][j] = 0ull;

    for (int k0 = k0base; k0 < kend; k0 += 8) {
        float4 ra = *(const float4*)(Aptr + k0);
        float4 rb = bOk ? *(const float4*)(Bptr + (long long)(k0 + bRow) * ldb)
                        : make_float4(0.f, 0.f, 0.f, 0.f);
        __syncthreads();
        As[aCol + 0][aRow] = ra.x;
        As[aCol + 1][aRow] = ra.y;
        As[aCol + 2][aRow] = ra.z;
        As[aCol + 3][aRow] = ra.w;
        *(float4*)&Bs[bRow][bCol] = rb;
        __syncthreads();

#pragma unroll
        for (int kk = 0; kk < 8; ++kk) {
            const float4 a0 = *(const float4*)&As[kk][ty * 8];
            const float4 a1 = *(const float4*)&As[kk][ty * 8 + 4];
            const ulonglong2 bq0 = *(const ulonglong2*)&Bs[kk][tx * 8];
            const ulonglong2 bq1 = *(const ulonglong2*)&Bs[kk][tx * 8 + 4];
            const float av[8] = {a0.x, a0.y, a0.z, a0.w, a1.x, a1.y, a1.z, a1.w};
#pragma unroll
            for (int i = 0; i < 8; i++) {
                const unsigned long long ad = dup2(av[i]);
                fma2(acc[i][0], ad, bq0.x);
                fma2(acc[i][1], ad, bq0.y);
                fma2(acc[i][2], ad, bq1.x);
                fma2(acc[i][3], ad, bq1.y);
            }
        }
    }

    const int crow0 = by * 128 + ty * 8;
    const int ccol0 = bx * 128 + tx * 8;
#pragma unroll
    for (int i = 0; i < 8; i++) {
        float v[8];
        upk2(acc[i][0], v[0], v[1]);
        upk2(acc[i][1], v[2], v[3]);
        upk2(acc[i][2], v[4], v[5]);
        upk2(acc[i][3], v[6], v[7]);
        float* crow = C + (long long)(crow0 + i) * ldc;
        if (ccol0 < N)
            *(float4*)(crow + ccol0) = make_float4(v[0], v[1], v[2], v[3]);
        if (ccol0 + 4 < N)
            *(float4*)(crow + ccol0 + 4) = make_float4(v[4], v[5], v[6], v[7]);
    }
}

// ---------------------------------------------------------------------------
// A = -exp(A_log)
// ---------------------------------------------------------------------------
__global__ void prep_kernel(const float* __restrict__ A_log) {
    const int i = blockIdx.x * 256 + threadIdx.x;
    g_A[i] = -expf(A_log[i]);
}

// ---------------------------------------------------------------------------
// depthwise causal conv1d (kw=4) + SiLU; input = g_xz[:, :DI], out = g_u
// ---------------------------------------------------------------------------
__global__ void __launch_bounds__(256)
conv_silu_kernel(const float* __restrict__ ck, const float* __restrict__ cb) {
    const int idx = blockIdx.x * 256 + threadIdx.x;   // < NT*DI
    const int d = idx & (DI - 1);
    const int t = idx >> 11;                          // token = b*L + l
    const int l = t & (LSEQ - 1);
    float acc = cb[d];
#pragma unroll
    for (int k = 0; k < 4; k++) {
        const int ll = l + k - 3;
        if (ll >= 0)
            acc = fmaf(g_xz[(long long)(t + k - 3) * (2 * DI) + d],
                       ck[k * DI + d], acc);
    }
    g_u[idx] = acc * (1.0f / (1.0f + __expf(-acc)));
}

// ---------------------------------------------------------------------------
// split-K reductions
// ---------------------------------------------------------------------------
__global__ void reduce8_kernel() {
    const int i = blockIdx.x * 256 + threadIdx.x;     // NT*XPN
    float s = 0.f;
#pragma unroll
    for (int k = 0; k < 8; k++) s += g_pxd[(long long)k * (NT * XPN) + i];
    g_xdbl[i] = s;
}
__global__ void reduce2_kernel(float* __restrict__ out) {
    const int i = blockIdx.x * 256 + threadIdx.x;     // NT*DM
    out[i] = g_pout[i] + g_pout[NT * DM + i];
}

// ---------------------------------------------------------------------------
// selective scan: 8 threads per channel (2 states each), shfl reduce,
// one-step prefetch; fused skip (u*D) and gating (* silu(z)).
// grid: (DI/16, BATCH), block 128.
// ---------------------------------------------------------------------------
__global__ void __launch_bounds__(128)
scan_kernel(const float* __restrict__ Dp) {
    const int tid = threadIdx.x;
    const int sub = tid & 7;                          // state pair index
    const int dd  = blockIdx.x * 16 + (tid >> 3);     // channel
    const long long t0 = (long long)blockIdx.y * LSEQ;

    const float a0 = g_A[dd * NSTATE + sub * 2 + 0];
    const float a1 = g_A[dd * NSTATE + sub * 2 + 1];
    const float Dv = Dp[dd];
    float h0 = 0.f, h1 = 0.f;

    // prefetch step 0
    float  dt_n = g_dt[t0 * DI + dd];
    float  u_n  = g_u [t0 * DI + dd];
    float  z_n  = g_xz[t0 * (2 * DI) + DI + dd];
    float2 B_n  = *(const float2*)&g_xdbl[t0 * XPN + DTR + sub * 2];
    float2 C_n  = *(const float2*)&g_xdbl[t0 * XPN + DTR + NSTATE + sub * 2];

    for (int l = 0; l < LSEQ; ++l) {
        const float  dtc = dt_n, uc = u_n, zc = z_n;
        const float2 Bc = B_n, Cc = C_n;
        if (l + 1 < LSEQ) {
            const long long tn = t0 + l + 1;
            dt_n = g_dt[tn * DI + dd];
            u_n  = g_u [tn * DI + dd];
            z_n  = g_xz[tn * (2 * DI) + DI + dd];
            B_n  = *(const float2*)&g_xdbl[tn * XPN + DTR + sub * 2];
            C_n  = *(const float2*)&g_xdbl[tn * XPN + DTR + NSTATE + sub * 2];
        }
        const float dtu = dtc * uc;
        h0 = fmaf(__expf(dtc * a0), h0, dtu * Bc.x);
        h1 = fmaf(__expf(dtc * a1), h1, dtu * Bc.y);
        float y = fmaf(h0, Cc.x, h1 * Cc.y);
        y += __shfl_xor_sync(0xffffffffu, y, 1);
        y += __shfl_xor_sync(0xffffffffu, y, 2);
        y += __shfl_xor_sync(0xffffffffu, y, 4);
        if (sub == 0) {
            const float sz = zc * (1.0f / (1.0f + __expf(-zc)));
            g_ys[(t0 + l) * DI + dd] = (y + uc * Dv) * sz;
        }
    }
}

// ---------------------------------------------------------------------------
// host launcher (graph-capturable: launches only)
// ---------------------------------------------------------------------------
extern "C" void kernel_launch(void* const* d_in, const int* in_sizes, int n_in,
                              void* d_out, int out_size) {
    const float* x       = (const float*)d_in[0];
    const float* W_in    = (const float*)d_in[1];
    const float* conv_k  = (const float*)d_in[2];
    const float* conv_b  = (const float*)d_in[3];
    const float* W_xproj = (const float*)d_in[4];
    const float* W_dt    = (const float*)d_in[5];
    const float* b_dt    = (const float*)d_in[6];
    const float* A_log   = (const float*)d_in[7];
    const float* Dp      = (const float*)d_in[8];
    const float* W_out   = (const float*)d_in[9];
    float* out = (float*)d_out;

    float *xz, *u, *xdbl, *dt, *ys, *pxd, *pout;
    cudaGetSymbolAddress((void**)&xz,   g_xz);
    cudaGetSymbolAddress((void**)&u,    g_u);
    cudaGetSymbolAddress((void**)&xdbl, g_xdbl);
    cudaGetSymbolAddress((void**)&dt,   g_dt);
    cudaGetSymbolAddress((void**)&ys,   g_ys);
    cudaGetSymbolAddress((void**)&pxd,  g_pxd);
    cudaGetSymbolAddress((void**)&pout, g_pout);

    // 0) A = -exp(A_log)
    prep_kernel<<<(DI * NSTATE) / 256, 256>>>(A_log);

    // 1) in_proj: xz = x @ W_in           (2048 x 4096, K=1024) — tensor tf32
    tgemm_tf32<0><<<dim3(2 * DI / 128, NT / 128, 1), 256>>>(
        x, W_in, xz, NT, 2 * DI, DM, DM, 2 * DI, 2 * DI,
        DM, 0, nullptr);

    // 2) depthwise conv + SiLU -> u
    conv_silu_kernel<<<(NT * DI) / 256, 256>>>(conv_k, conv_b);

    // 3) xdbl = u @ W_xproj               (2048 x 160, K=2048), split-K 8 (SIMT)
    sgemm128<<<dim3(2, NT / 128, 8), 256>>>(
        u, W_xproj, pxd, NT, XPN, DI, DI, XPN, XPN,
        DI / 8, (long long)NT * XPN);
    reduce8_kernel<<<(NT * XPN) / 256, 256>>>();

    // 4) dt = softplus(xdbl[:, :128] @ W_dt + b_dt)   (2048 x 2048, K=128) — tensor
    tgemm_tf32<1><<<dim3(DI / 128, NT / 128, 1), 256>>>(
        xdbl, W_dt, dt, NT, DI, DTR, XPN, DI, DI,
        DTR, 0, b_dt);

    // 5) selective scan (fused skip + gate) -> ys
    scan_kernel<<<dim3(DI / 16, 2), 128>>>(Dp);

    // 6) out = ys @ W_out                 (2048 x 1024, K=2048), split-K 2 — tensor
    tgemm_tf32<0><<<dim3(DM / 128, NT / 128, 2), 256>>>(
        ys, W_out, pout, NT, DM, DI, DI, DM, DM,
        DI / 2, (long long)NT * DM, nullptr);
    reduce2_kernel<<<(NT * DM) / 256, 256>>>(out);
}

// round 10
// speedup vs baseline: 1.0010x; 1.0010x over previous
#include <cuda_runtime.h>
#include <cuda_bf16.h>
#include <cstdint>
#include <math.h>

// ---------------------------------------------------------------------------
// Fixed problem shape:
//   BATCH=2, SEQLEN=1024, D_MODEL=1024, D_INNER=2048, DT_RANK=128, D_STATE=16,
//   D_CONV=4. Tokens NT = 2048.
// ---------------------------------------------------------------------------
#define DI      2048
#define DM      1024
#define LSEQ    1024
#define NT      2048
#define NSTATE  16
#define DTR     128
#define XPN     160      // DT_RANK + 2*D_STATE

// ----------------------- device scratch (no mallocs) -----------------------
__device__ float g_xz   [NT * 2 * DI];      // in_proj out: [x_in | z]
__device__ float g_u    [NT * DI];          // silu(conv(x_in))
__device__ float g_xdbl [NT * XPN];         // u @ W_xproj
__device__ float g_dt   [NT * DI];          // softplus(...)
__device__ float g_ys   [NT * DI];          // gated scan output
__device__ float g_A    [DI * NSTATE];      // A = -exp(A_log)
__device__ float g_pxd  [8 * NT * XPN];     // split-K partials (xproj)
__device__ float g_pout [2 * NT * DM];      // split-K partials (out)

// ----------------------- misc device helpers -------------------------------
__device__ __forceinline__ float softplus_f(float x) {
    if (x > 20.0f) return x;
    return log1pf(__expf(x));
}

// ----------------------- packed f32x2 helpers (SIMT GEMM) ------------------
__device__ __forceinline__ unsigned long long dup2(float v) {
    unsigned long long r;
    asm("mov.b64 %0, {%1, %1};" : "=l"(r) : "f"(v));
    return r;
}
__device__ __forceinline__ void fma2(unsigned long long& a,
                                     unsigned long long x,
                                     unsigned long long y) {
    asm("fma.rn.f32x2 %0, %1, %2, %0;" : "+l"(a) : "l"(x), "l"(y));
}
__device__ __forceinline__ void upk2(unsigned long long v, float& lo, float& hi) {
    asm("mov.b64 {%0, %1}, %2;" : "=f"(lo), "=f"(hi) : "l"(v));
}

// ----------------------- tf32 tensor helpers -------------------------------
__device__ __forceinline__ void split_tf32(float v, unsigned& hi, unsigned& lo) {
    unsigned h;
    asm("cvt.rna.tf32.f32 %0, %1;" : "=r"(h) : "f"(v));
    float r = v - __uint_as_float(h);
    unsigned l;
    asm("cvt.rna.tf32.f32 %0, %1;" : "=r"(l) : "f"(r));
    hi = h; lo = l;
}
__device__ __forceinline__ void mma_tf32(float* d, const unsigned* a, const unsigned* b) {
    asm volatile(
        "mma.sync.aligned.m16n8k8.row.col.f32.tf32.tf32.f32 "
        "{%0,%1,%2,%3}, {%4,%5,%6,%7}, {%8,%9}, {%0,%1,%2,%3};\n"
        : "+f"(d[0]), "+f"(d[1]), "+f"(d[2]), "+f"(d[3])
        : "r"(a[0]), "r"(a[1]), "r"(a[2]), "r"(a[3]), "r"(b[0]), "r"(b[1]));
}

// ---------------------------------------------------------------------------
// Tensor-core tf32 GEMM with 3-term precision compensation.
//   C[M,N] = A[M,K] @ B[K,N], row-major, fp32 in/out, rel err ~1e-7.
//   128x128 block tile, BK=16, 256 threads = 8 warps (4x2), warp = 32x64.
//   Requires: M%128==0, N%128==0, Kslice%16==0.
//   EPI==1 -> softplus(acc + bias[col]).
//   blockIdx.z = split-K slice, writes C + bz*cSliceStride.
// ---------------------------------------------------------------------------
template <int EPI>
__global__ void __launch_bounds__(256)
tgemm_tf32(const float* __restrict__ A, const float* __restrict__ B,
           float* __restrict__ C, int M, int N, int K,
           int lda, int ldb, int ldc,
           int Kslice, long long cSliceStride, const float* __restrict__ bias)
{
    // padded layouts: A stride 20 (bank=(20r+c)%32 hits all banks),
    //                 B stride 136 (bank=(8c+n)%32 hits all banks)
    __shared__ __align__(16) float As[2][128 * 20];
    __shared__ __align__(16) float Bs[2][16 * 136];

    const int tid  = threadIdx.x;
    const int lane = tid & 31;
    const int wid  = tid >> 5;
    const int wm   = wid & 3;        // 4 warps in M
    const int wn   = wid >> 2;       // 2 warps in N
    const int bx = blockIdx.x, by = blockIdx.y, bz = blockIdx.z;

    C += (long long)bz * cSliceStride;
    const int k0 = bz * Kslice;
    const int KT = Kslice >> 4;      // k-tiles of 16

    // global load mapping: A 128x16 (2 float4/thread), B 16x128 (2 float4/thread)
    const int aRow = tid >> 1;
    const int aK   = (tid & 1) * 8;
    const int bRow = tid >> 4;
    const int bCol = (tid & 15) * 8;

    const float* Ag = A + (long long)(by * 128 + aRow) * lda + k0 + aK;
    const float* Bg = B + (long long)(k0 + bRow) * ldb + bx * 128 + bCol;

    float acc[2][8][4];
#pragma unroll
    for (int mt = 0; mt < 2; mt++)
#pragma unroll
        for (int nt = 0; nt < 8; nt++)
#pragma unroll
            for (int j = 0; j < 4; j++) acc[mt][nt][j] = 0.f;

    // preload tile 0 into smem buffer 0
    {
        float4 pa0 = *(const float4*)(Ag);
        float4 pa1 = *(const float4*)(Ag + 4);
        float4 pb0 = *(const float4*)(Bg);
        float4 pb1 = *(const float4*)(Bg + 4);
        float* as = &As[0][aRow * 20 + aK];
        *(float4*)as = pa0; *(float4*)(as + 4) = pa1;
        float* bsw = &Bs[0][bRow * 136 + bCol];
        *(float4*)bsw = pb0; *(float4*)(bsw + 4) = pb1;
    }

    int cur = 0;
    const int frow = lane >> 2;      // 0..7
    const int fcol = lane & 3;       // 0..3

    for (int kt = 0; kt < KT; ++kt) {
        __syncthreads();

        float4 pa0, pa1, pb0, pb1;
        const bool more = (kt + 1 < KT);
        if (more) {
            const float* Ag2 = Ag + (kt + 1) * 16;
            const float* Bg2 = Bg + (long long)(kt + 1) * 16 * ldb;
            pa0 = *(const float4*)(Ag2);
            pa1 = *(const float4*)(Ag2 + 4);
            pb0 = *(const float4*)(Bg2);
            pb1 = *(const float4*)(Bg2 + 4);
        }

        const float* as = As[cur];
        const float* bs = Bs[cur];
#pragma unroll
        for (int ks = 0; ks < 2; ++ks) {
            const int c = ks * 8 + fcol;
            unsigned ah[2][4], al[2][4];
#pragma unroll
            for (int mt = 0; mt < 2; mt++) {
                const int r = wm * 32 + mt * 16 + frow;
                split_tf32(as[r * 20 + c],           ah[mt][0], al[mt][0]);
                split_tf32(as[(r + 8) * 20 + c],     ah[mt][1], al[mt][1]);
                split_tf32(as[r * 20 + c + 4],       ah[mt][2], al[mt][2]);
                split_tf32(as[(r + 8) * 20 + c + 4], ah[mt][3], al[mt][3]);
            }
#pragma unroll
            for (int nt = 0; nt < 8; nt++) {
                const int col = wn * 64 + nt * 8 + frow;
                unsigned bh[2], bl[2];
                split_tf32(bs[c * 136 + col],       bh[0], bl[0]);
                split_tf32(bs[(c + 4) * 136 + col], bh[1], bl[1]);
#pragma unroll
                for (int mt = 0; mt < 2; mt++) {
                    mma_tf32(acc[mt][nt], ah[mt], bh);   // hi*hi
                    mma_tf32(acc[mt][nt], al[mt], bh);   // lo*hi
                    mma_tf32(acc[mt][nt], ah[mt], bl);   // hi*lo
                }
            }
        }

        if (more) {
            float* asw = &As[cur ^ 1][aRow * 20 + aK];
            *(float4*)asw = pa0; *(float4*)(asw + 4) = pa1;
            float* bsw = &Bs[cur ^ 1][bRow * 136 + bCol];
            *(float4*)bsw = pb0; *(float4*)(bsw + 4) = pb1;
            cur ^= 1;
        }
    }

    // epilogue
    const int rbase = by * 128 + wm * 32;
    const int cbase = bx * 128 + wn * 64;
#pragma unroll
    for (int mt = 0; mt < 2; mt++) {
#pragma unroll
        for (int nt = 0; nt < 8; nt++) {
            const int r  = rbase + mt * 16 + frow;
            const int cc = cbase + nt * 8 + fcol * 2;
            float v0 = acc[mt][nt][0], v1 = acc[mt][nt][1];
            float v2 = acc[mt][nt][2], v3 = acc[mt][nt][3];
            if (EPI == 1) {
                const float b0 = bias[cc], b1 = bias[cc + 1];
                v0 = softplus_f(v0 + b0); v1 = softplus_f(v1 + b1);
                v2 = softplus_f(v2 + b0); v3 = softplus_f(v3 + b1);
            }
            *(float2*)&C[(long long)r * ldc + cc]       = make_float2(v0, v1);
            *(float2*)&C[(long long)(r + 8) * ldc + cc] = make_float2(v2, v3);
        }
    }
}

// ---------------------------------------------------------------------------
// SIMT fp32 GEMM (f32x2) — kept for xproj (N=160 not a multiple of 128).
// ---------------------------------------------------------------------------
__global__ void __launch_bounds__(256)
sgemm128(const float* __restrict__ A, const float* __restrict__ B,
         float* __restrict__ C, int M, int N, int K,
         int lda, int ldb, int ldc,
         int Kslice, long long cSliceStride)
{
    __shared__ __align__(16) float As[8][128];
    __shared__ __align__(16) float Bs[8][128];

    const int tid = threadIdx.x;
    const int bx = blockIdx.x, by = blockIdx.y, bz = blockIdx.z;
    C += (long long)bz * cSliceStride;
    const int k0base = bz * Kslice;
    const int kend   = min(K, k0base + Kslice);

    const int aRow = tid >> 1;
    const int aCol = (tid & 1) << 2;
    const int bRow = tid >> 5;
    const int bCol = (tid & 31) << 2;
    const int tx   = tid & 15;
    const int ty   = tid >> 4;

    const int  gBCol = bx * 128 + bCol;
    const bool bOk   = (gBCol < N);

    const float* Aptr = A + (long long)(by * 128 + aRow) * lda + aCol;
    const float* Bptr = B + gBCol;

    unsigned long long acc[8][4];
#pragma unroll
    for (int i = 0; i < 8; i++)
#pragma unroll
        for (int j = 0; j < 4; j++) acc[i][j] = 0ull;

    for (int k0 = k0base; k0 < kend; k0 += 8) {
        float4 ra = *(const float4*)(Aptr + k0);
        float4 rb = bOk ? *(const float4*)(Bptr + (long long)(k0 + bRow) * ldb)
                        : make_float4(0.f, 0.f, 0.f, 0.f);
        __syncthreads();
        As[aCol + 0][aRow] = ra.x;
        As[aCol + 1][aRow] = ra.y;
        As[aCol + 2][aRow] = ra.z;
        As[aCol + 3][aRow] = ra.w;
        *(float4*)&Bs[bRow][bCol] = rb;
        __syncthreads();

#pragma unroll
        for (int kk = 0; kk < 8; ++kk) {
            const float4 a0 = *(const float4*)&As[kk][ty * 8];
            const float4 a1 = *(const float4*)&As[kk][ty * 8 + 4];
            const ulonglong2 bq0 = *(const ulonglong2*)&Bs[kk][tx * 8];
            const ulonglong2 bq1 = *(const ulonglong2*)&Bs[kk][tx * 8 + 4];
            const float av[8] = {a0.x, a0.y, a0.z, a0.w, a1.x, a1.y, a1.z, a1.w};
#pragma unroll
            for (int i = 0; i < 8; i++) {
                const unsigned long long ad = dup2(av[i]);
                fma2(acc[i][0], ad, bq0.x);
                fma2(acc[i][1], ad, bq0.y);
                fma2(acc[i][2], ad, bq1.x);
                fma2(acc[i][3], ad, bq1.y);
            }
        }
    }

    const int crow0 = by * 128 + ty * 8;
    const int ccol0 = bx * 128 + tx * 8;
#pragma unroll
    for (int i = 0; i < 8; i++) {
        float v[8];
        upk2(acc[i][0], v[0], v[1]);
        upk2(acc[i][1], v[2], v[3]);
        upk2(acc[i][2], v[4], v[5]);
        upk2(acc[i][3], v[6], v[7]);
        float* crow = C + (long long)(crow0 + i) * ldc;
        if (ccol0 < N)
            *(float4*)(crow + ccol0) = make_float4(v[0], v[1], v[2], v[3]);
        if (ccol0 + 4 < N)
            *(float4*)(crow + ccol0 + 4) = make_float4(v[4], v[5], v[6], v[7]);
    }
}

// ---------------------------------------------------------------------------
// A = -exp(A_log)
// ---------------------------------------------------------------------------
__global__ void prep_kernel(const float* __restrict__ A_log) {
    const int i = blockIdx.x * 256 + threadIdx.x;
    g_A[i] = -expf(A_log[i]);
}

// ---------------------------------------------------------------------------
// depthwise causal conv1d (kw=4) + SiLU; input = g_xz[:, :DI], out = g_u
// ---------------------------------------------------------------------------
__global__ void __launch_bounds__(256)
conv_silu_kernel(const float* __restrict__ ck, const float* __restrict__ cb) {
    const int idx = blockIdx.x * 256 + threadIdx.x;   // < NT*DI
    const int d = idx & (DI - 1);
    const int t = idx >> 11;                          // token = b*L + l
    const int l = t & (LSEQ - 1);
    float acc = cb[d];
#pragma unroll
    for (int k = 0; k < 4; k++) {
        const int ll = l + k - 3;
        if (ll >= 0)
            acc = fmaf(g_xz[(long long)(t + k - 3) * (2 * DI) + d],
                       ck[k * DI + d], acc);
    }
    g_u[idx] = acc * (1.0f / (1.0f + __expf(-acc)));
}

// ---------------------------------------------------------------------------
// split-K reductions
// ---------------------------------------------------------------------------
__global__ void reduce8_kernel() {
    const int i = blockIdx.x * 256 + threadIdx.x;     // NT*XPN
    float s = 0.f;
#pragma unroll
    for (int k = 0; k < 8; k++) s += g_pxd[(long long)k * (NT * XPN) + i];
    g_xdbl[i] = s;
}
__global__ void reduce2_kernel(float* __restrict__ out) {
    const int i = blockIdx.x * 256 + threadIdx.x;     // NT*DM
    out[i] = g_pout[i] + g_pout[NT * DM + i];
}

// ---------------------------------------------------------------------------
// selective scan: 8 threads per channel (2 states each), shfl reduce,
// one-step prefetch; fused skip (u*D) and gating (* silu(z)).
// grid: (DI/16, BATCH), block 128.
// ---------------------------------------------------------------------------
__global__ void __launch_bounds__(128)
scan_kernel(const float* __restrict__ Dp) {
    const int tid = threadIdx.x;
    const int sub = tid & 7;                          // state pair index
    const int dd  = blockIdx.x * 16 + (tid >> 3);     // channel
    const long long t0 = (long long)blockIdx.y * LSEQ;

    const float a0 = g_A[dd * NSTATE + sub * 2 + 0];
    const float a1 = g_A[dd * NSTATE + sub * 2 + 1];
    const float Dv = Dp[dd];
    float h0 = 0.f, h1 = 0.f;

    // prefetch step 0
    float  dt_n = g_dt[t0 * DI + dd];
    float  u_n  = g_u [t0 * DI + dd];
    float  z_n  = g_xz[t0 * (2 * DI) + DI + dd];
    float2 B_n  = *(const float2*)&g_xdbl[t0 * XPN + DTR + sub * 2];
    float2 C_n  = *(const float2*)&g_xdbl[t0 * XPN + DTR + NSTATE + sub * 2];

    for (int l = 0; l < LSEQ; ++l) {
        const float  dtc = dt_n, uc = u_n, zc = z_n;
        const float2 Bc = B_n, Cc = C_n;
        if (l + 1 < LSEQ) {
            const long long tn = t0 + l + 1;
            dt_n = g_dt[tn * DI + dd];
            u_n  = g_u [tn * DI + dd];
            z_n  = g_xz[tn * (2 * DI) + DI + dd];
            B_n  = *(const float2*)&g_xdbl[tn * XPN + DTR + sub * 2];
            C_n  = *(const float2*)&g_xdbl[tn * XPN + DTR + NSTATE + sub * 2];
        }
        const float dtu = dtc * uc;
        h0 = fmaf(__expf(dtc * a0), h0, dtu * Bc.x);
        h1 = fmaf(__expf(dtc * a1), h1, dtu * Bc.y);
        float y = fmaf(h0, Cc.x, h1 * Cc.y);
        y += __shfl_xor_sync(0xffffffffu, y, 1);
        y += __shfl_xor_sync(0xffffffffu, y, 2);
        y += __shfl_xor_sync(0xffffffffu, y, 4);
        if (sub == 0) {
            const float sz = zc * (1.0f / (1.0f + __expf(-zc)));
            g_ys[(t0 + l) * DI + dd] = (y + uc * Dv) * sz;
        }
    }
}

// ---------------------------------------------------------------------------
// host launcher (graph-capturable: launches only)
// ---------------------------------------------------------------------------
extern "C" void kernel_launch(void* const* d_in, const int* in_sizes, int n_in,
                              void* d_out, int out_size) {
    const float* x       = (const float*)d_in[0];
    const float* W_in    = (const float*)d_in[1];
    const float* conv_k  = (const float*)d_in[2];
    const float* conv_b  = (const float*)d_in[3];
    const float* W_xproj = (const float*)d_in[4];
    const float* W_dt    = (const float*)d_in[5];
    const float* b_dt    = (const float*)d_in[6];
    const float* A_log   = (const float*)d_in[7];
    const float* Dp      = (const float*)d_in[8];
    const float* W_out   = (const float*)d_in[9];
    float* out = (float*)d_out;

    float *xz, *u, *xdbl, *dt, *ys, *pxd, *pout;
    cudaGetSymbolAddress((void**)&xz,   g_xz);
    cudaGetSymbolAddress((void**)&u,    g_u);
    cudaGetSymbolAddress((void**)&xdbl, g_xdbl);
    cudaGetSymbolAddress((void**)&dt,   g_dt);
    cudaGetSymbolAddress((void**)&ys,   g_ys);
    cudaGetSymbolAddress((void**)&pxd,  g_pxd);
    cudaGetSymbolAddress((void**)&pout, g_pout);

    // 0) A = -exp(A_log)
    prep_kernel<<<(DI * NSTATE) / 256, 256>>>(A_log);

    // 1) in_proj: xz = x @ W_in           (2048 x 4096, K=1024) — tensor tf32
    tgemm_tf32<0><<<dim3(2 * DI / 128, NT / 128, 1), 256>>>(
        x, W_in, xz, NT, 2 * DI, DM, DM, 2 * DI, 2 * DI,
        DM, 0, nullptr);

    // 2) depthwise conv + SiLU -> u
    conv_silu_kernel<<<(NT * DI) / 256, 256>>>(conv_k, conv_b);

    // 3) xdbl = u @ W_xproj               (2048 x 160, K=2048), split-K 8 (SIMT)
    sgemm128<<<dim3(2, NT / 128, 8), 256>>>(
        u, W_xproj, pxd, NT, XPN, DI, DI, XPN, XPN,
        DI / 8, (long long)NT * XPN);
    reduce8_kernel<<<(NT * XPN) / 256, 256>>>();

    // 4) dt = softplus(xdbl[:, :128] @ W_dt + b_dt)   (2048 x 2048, K=128) — tensor
    tgemm_tf32<1><<<dim3(DI / 128, NT / 128, 1), 256>>>(
        xdbl, W_dt, dt, NT, DI, DTR, XPN, DI, DI,
        DTR, 0, b_dt);

    // 5) selective scan (fused skip + gate) -> ys
    scan_kernel<<<dim3(DI / 16, 2), 128>>>(Dp);

    // 6) out = ys @ W_out                 (2048 x 1024, K=2048), split-K 2 — tensor
    tgemm_tf32<0><<<dim3(DM / 128, NT / 128, 2), 256>>>(
        ys, W_out, pout, NT, DM, DI, DI, DM, DM,
        DI / 2, (long long)NT * DM, nullptr);
    reduce2_kernel<<<(NT * DM) / 256, 256>>>(out);
}

// round 11
// speedup vs baseline: 1.0929x; 1.0918x over previous
#include <cuda_runtime.h>
#include <cuda_bf16.h>
#include <cstdint>
#include <math.h>

// ---------------------------------------------------------------------------
// Fixed problem shape:
//   BATCH=2, SEQLEN=1024, D_MODEL=1024, D_INNER=2048, DT_RANK=128, D_STATE=16,
//   D_CONV=4. Tokens NT = 2048.
// ---------------------------------------------------------------------------
#define DI      2048
#define DM      1024
#define LSEQ    1024
#define NT      2048
#define NSTATE  16
#define DTR     128
#define XPN     160      // DT_RANK + 2*D_STATE

// ----------------------- device scratch (no mallocs) -----------------------
__device__ float g_xz   [NT * 2 * DI];      // in_proj out: [x_in | z]
__device__ float g_u    [NT * DI];          // silu(conv(x_in))
__device__ float g_xdbl [NT * XPN];         // u @ W_xproj
__device__ float g_dt   [NT * DI];          // softplus(...)
__device__ float g_ys   [NT * DI];          // gated scan output
__device__ float g_A    [DI * NSTATE];      // A = -exp(A_log)
__device__ float g_pxd  [8 * NT * XPN];     // split-K partials (xproj)
__device__ float g_pout [2 * NT * DM];      // split-K partials (out)

// ----------------------- misc device helpers -------------------------------
__device__ __forceinline__ float softplus_f(float x) {
    if (x > 20.0f) return x;
    return log1pf(__expf(x));
}

// ----------------------- tf32 tensor helpers -------------------------------
__device__ __forceinline__ void split_tf32(float v, unsigned& hi, unsigned& lo) {
    unsigned h;
    asm("cvt.rna.tf32.f32 %0, %1;" : "=r"(h) : "f"(v));
    float r = v - __uint_as_float(h);
    unsigned l;
    asm("cvt.rna.tf32.f32 %0, %1;" : "=r"(l) : "f"(r));
    hi = h; lo = l;
}
__device__ __forceinline__ void split_store4(float4 v, unsigned* hi, unsigned* lo) {
    unsigned h0, l0, h1, l1, h2, l2, h3, l3;
    split_tf32(v.x, h0, l0); split_tf32(v.y, h1, l1);
    split_tf32(v.z, h2, l2); split_tf32(v.w, h3, l3);
    *(uint4*)hi = make_uint4(h0, h1, h2, h3);
    *(uint4*)lo = make_uint4(l0, l1, l2, l3);
}
__device__ __forceinline__ void mma_tf32(float* d, const unsigned* a, const unsigned* b) {
    asm volatile(
        "mma.sync.aligned.m16n8k8.row.col.f32.tf32.tf32.f32 "
        "{%0,%1,%2,%3}, {%4,%5,%6,%7}, {%8,%9}, {%0,%1,%2,%3};\n"
        : "+f"(d[0]), "+f"(d[1]), "+f"(d[2]), "+f"(d[3])
        : "r"(a[0]), "r"(a[1]), "r"(a[2]), "r"(a[3]), "r"(b[0]), "r"(b[1]));
}

// SMEM partition constants (in 4-byte words)
#define AS_W  (128 * 20)     // 2560 per buffer (stride-20 pad: conflict-free)
#define BS_W  (16 * 136)     // 2176 per buffer (stride-136 pad: conflict-free)
#define TG_SMEM_BYTES ((2 * AS_W * 2 + 2 * BS_W * 2) * 4)   // 75776

// ---------------------------------------------------------------------------
// Tensor-core tf32 GEMM, 3-term compensation, hi/lo PRE-SPLIT in SMEM.
//   C[M,N] = A[M,K] @ B[K,N], row-major fp32 in/out.
//   128x128 block tile, BK=16, 256 threads = 8 warps (4x2), warp = 32x64.
//   Requires M%128==0, Kslice%16==0, N%8==0 (GUARDN=1 allows N not mult of 128).
//   EPI==1 -> softplus(acc + bias[col]). blockIdx.z = split-K slice.
// ---------------------------------------------------------------------------
template <int EPI, int GUARDN>
__global__ void __launch_bounds__(256, 2)
tgemm2(const float* __restrict__ A, const float* __restrict__ B,
       float* __restrict__ C, int M, int N, int K,
       int lda, int ldb, int ldc,
       int Kslice, long long cSliceStride, const float* __restrict__ bias)
{
    extern __shared__ unsigned smem_u[];
    unsigned* AsH = smem_u;                 // [2][AS_W]
    unsigned* AsL = AsH + 2 * AS_W;
    unsigned* BsH = AsL + 2 * AS_W;         // [2][BS_W]
    unsigned* BsL = BsH + 2 * BS_W;

    const int tid  = threadIdx.x;
    const int lane = tid & 31;
    const int wid  = tid >> 5;
    const int wm   = wid & 3;               // 4 warps in M
    const int wn   = wid >> 2;               // 2 warps in N
    const int bx = blockIdx.x, by = blockIdx.y, bz = blockIdx.z;

    C += (long long)bz * cSliceStride;
    const int k0 = bz * Kslice;
    const int KT = Kslice >> 4;

    // global load mapping: A 128x16 (2 float4/thread), B 16x128 (2 float4/thread)
    const int aRow = tid >> 1;
    const int aK   = (tid & 1) * 8;
    const int bRow = tid >> 4;
    const int bCol = (tid & 15) * 8;

    const int  gBCol = bx * 128 + bCol;
    const bool bOk   = !GUARDN || (gBCol < N);   // N%8==0 -> covers both float4

    const float* Ag = A + (long long)(by * 128 + aRow) * lda + k0 + aK;
    const float* Bg = B + (long long)(k0 + bRow) * ldb + gBCol;

    float acc[2][8][4];
#pragma unroll
    for (int mt = 0; mt < 2; mt++)
#pragma unroll
        for (int nt = 0; nt < 8; nt++)
#pragma unroll
            for (int j = 0; j < 4; j++) acc[mt][nt][j] = 0.f;

    // preload tile 0 into buffer 0 (split at store time)
    {
        float4 pa0 = *(const float4*)(Ag);
        float4 pa1 = *(const float4*)(Ag + 4);
        float4 pb0 = bOk ? *(const float4*)(Bg)     : make_float4(0,0,0,0);
        float4 pb1 = bOk ? *(const float4*)(Bg + 4) : make_float4(0,0,0,0);
        const int ai = aRow * 20 + aK;
        const int bi = bRow * 136 + bCol;
        split_store4(pa0, &AsH[ai],     &AsL[ai]);
        split_store4(pa1, &AsH[ai + 4], &AsL[ai + 4]);
        split_store4(pb0, &BsH[bi],     &BsL[bi]);
        split_store4(pb1, &BsH[bi + 4], &BsL[bi + 4]);
    }

    int cur = 0;
    const int frow = lane >> 2;      // 0..7
    const int fcol = lane & 3;       // 0..3

    for (int kt = 0; kt < KT; ++kt) {
        __syncthreads();

        float4 pa0, pa1, pb0, pb1;
        const bool more = (kt + 1 < KT);
        if (more) {
            const float* Ag2 = Ag + (kt + 1) * 16;
            const float* Bg2 = Bg + (long long)(kt + 1) * 16 * ldb;
            pa0 = *(const float4*)(Ag2);
            pa1 = *(const float4*)(Ag2 + 4);
            pb0 = bOk ? *(const float4*)(Bg2)     : make_float4(0,0,0,0);
            pb1 = bOk ? *(const float4*)(Bg2 + 4) : make_float4(0,0,0,0);
        }

        const unsigned* ah_s = AsH + cur * AS_W;
        const unsigned* al_s = AsL + cur * AS_W;
        const unsigned* bh_s = BsH + cur * BS_W;
        const unsigned* bl_s = BsL + cur * BS_W;

#pragma unroll
        for (int ks = 0; ks < 2; ++ks) {
            const int c = ks * 8 + fcol;
            unsigned ah[2][4], al[2][4];
#pragma unroll
            for (int mt = 0; mt < 2; mt++) {
                const int r = wm * 32 + mt * 16 + frow;
                const int i0 = r * 20 + c;
                ah[mt][0] = ah_s[i0];            al[mt][0] = al_s[i0];
                ah[mt][1] = ah_s[i0 + 160];      al[mt][1] = al_s[i0 + 160];   // +8 rows
                ah[mt][2] = ah_s[i0 + 4];        al[mt][2] = al_s[i0 + 4];
                ah[mt][3] = ah_s[i0 + 164];      al[mt][3] = al_s[i0 + 164];
            }
#pragma unroll
            for (int nt = 0; nt < 8; nt++) {
                const int col = wn * 64 + nt * 8 + frow;
                unsigned bh[2], bl[2];
                bh[0] = bh_s[c * 136 + col];        bl[0] = bl_s[c * 136 + col];
                bh[1] = bh_s[(c + 4) * 136 + col];  bl[1] = bl_s[(c + 4) * 136 + col];
#pragma unroll
                for (int mt = 0; mt < 2; mt++) {
                    mma_tf32(acc[mt][nt], ah[mt], bh);   // hi*hi
                    mma_tf32(acc[mt][nt], al[mt], bh);   // lo*hi
                    mma_tf32(acc[mt][nt], ah[mt], bl);   // hi*lo
                }
            }
        }

        if (more) {
            const int nb = cur ^ 1;
            const int ai = aRow * 20 + aK;
            const int bi = bRow * 136 + bCol;
            split_store4(pa0, &AsH[nb * AS_W + ai],     &AsL[nb * AS_W + ai]);
            split_store4(pa1, &AsH[nb * AS_W + ai + 4], &AsL[nb * AS_W + ai + 4]);
            split_store4(pb0, &BsH[nb * BS_W + bi],     &BsL[nb * BS_W + bi]);
            split_store4(pb1, &BsH[nb * BS_W + bi + 4], &BsL[nb * BS_W + bi + 4]);
            cur = nb;
        }
    }

    // epilogue
    const int rbase = by * 128 + wm * 32;
    const int cbase = bx * 128 + wn * 64;
#pragma unroll
    for (int mt = 0; mt < 2; mt++) {
#pragma unroll
        for (int nt = 0; nt < 8; nt++) {
            const int r  = rbase + mt * 16 + frow;
            const int cc = cbase + nt * 8 + fcol * 2;
            if (GUARDN && cc >= N) continue;
            float v0 = acc[mt][nt][0], v1 = acc[mt][nt][1];
            float v2 = acc[mt][nt][2], v3 = acc[mt][nt][3];
            if (EPI == 1) {
                const float b0 = bias[cc], b1 = bias[cc + 1];
                v0 = softplus_f(v0 + b0); v1 = softplus_f(v1 + b1);
                v2 = softplus_f(v2 + b0); v3 = softplus_f(v3 + b1);
            }
            *(float2*)&C[(long long)r * ldc + cc]       = make_float2(v0, v1);
            *(float2*)&C[(long long)(r + 8) * ldc + cc] = make_float2(v2, v3);
        }
    }
}

// ---------------------------------------------------------------------------
// A = -exp(A_log)
// ---------------------------------------------------------------------------
__global__ void prep_kernel(const float* __restrict__ A_log) {
    const int i = blockIdx.x * 256 + threadIdx.x;
    g_A[i] = -expf(A_log[i]);
}

// ---------------------------------------------------------------------------
// depthwise causal conv1d (kw=4) + SiLU; input = g_xz[:, :DI], out = g_u
// ---------------------------------------------------------------------------
__global__ void __launch_bounds__(256)
conv_silu_kernel(const float* __restrict__ ck, const float* __restrict__ cb) {
    const int idx = blockIdx.x * 256 + threadIdx.x;   // < NT*DI
    const int d = idx & (DI - 1);
    const int t = idx >> 11;                          // token = b*L + l
    const int l = t & (LSEQ - 1);
    float acc = cb[d];
#pragma unroll
    for (int k = 0; k < 4; k++) {
        const int ll = l + k - 3;
        if (ll >= 0)
            acc = fmaf(g_xz[(long long)(t + k - 3) * (2 * DI) + d],
                       ck[k * DI + d], acc);
    }
    g_u[idx] = acc * (1.0f / (1.0f + __expf(-acc)));
}

// ---------------------------------------------------------------------------
// split-K reductions
// ---------------------------------------------------------------------------
__global__ void reduce8_kernel() {
    const int i = blockIdx.x * 256 + threadIdx.x;     // NT*XPN
    float s = 0.f;
#pragma unroll
    for (int k = 0; k < 8; k++) s += g_pxd[(long long)k * (NT * XPN) + i];
    g_xdbl[i] = s;
}
__global__ void reduce2_kernel(float* __restrict__ out) {
    const int i = blockIdx.x * 256 + threadIdx.x;     // NT*DM
    out[i] = g_pout[i] + g_pout[NT * DM + i];
}

// ---------------------------------------------------------------------------
// selective scan: 8 threads per channel (2 states each), shfl reduce,
// one-step prefetch; fused skip (u*D) and gating (* silu(z)).
// grid: (DI/32, BATCH), block 256 (32 channels/block) -> single wave (128 blocks).
// ---------------------------------------------------------------------------
__global__ void __launch_bounds__(256)
scan_kernel(const float* __restrict__ Dp) {
    const int tid = threadIdx.x;
    const int sub = tid & 7;                          // state pair index
    const int dd  = blockIdx.x * 32 + (tid >> 3);     // channel
    const long long t0 = (long long)blockIdx.y * LSEQ;

    const float a0 = g_A[dd * NSTATE + sub * 2 + 0];
    const float a1 = g_A[dd * NSTATE + sub * 2 + 1];
    const float Dv = Dp[dd];
    float h0 = 0.f, h1 = 0.f;

    // prefetch step 0
    float  dt_n = g_dt[t0 * DI + dd];
    float  u_n  = g_u [t0 * DI + dd];
    float  z_n  = g_xz[t0 * (2 * DI) + DI + dd];
    float2 B_n  = *(const float2*)&g_xdbl[t0 * XPN + DTR + sub * 2];
    float2 C_n  = *(const float2*)&g_xdbl[t0 * XPN + DTR + NSTATE + sub * 2];

    for (int l = 0; l < LSEQ; ++l) {
        const float  dtc = dt_n, uc = u_n, zc = z_n;
        const float2 Bc = B_n, Cc = C_n;
        if (l + 1 < LSEQ) {
            const long long tn = t0 + l + 1;
            dt_n = g_dt[tn * DI + dd];
            u_n  = g_u [tn * DI + dd];
            z_n  = g_xz[tn * (2 * DI) + DI + dd];
            B_n  = *(const float2*)&g_xdbl[tn * XPN + DTR + sub * 2];
            C_n  = *(const float2*)&g_xdbl[tn * XPN + DTR + NSTATE + sub * 2];
        }
        const float dtu = dtc * uc;
        h0 = fmaf(__expf(dtc * a0), h0, dtu * Bc.x);
        h1 = fmaf(__expf(dtc * a1), h1, dtu * Bc.y);
        float y = fmaf(h0, Cc.x, h1 * Cc.y);
        y += __shfl_xor_sync(0xffffffffu, y, 1);
        y += __shfl_xor_sync(0xffffffffu, y, 2);
        y += __shfl_xor_sync(0xffffffffu, y, 4);
        if (sub == 0) {
            const float sz = zc * (1.0f / (1.0f + __expf(-zc)));
            g_ys[(t0 + l) * DI + dd] = (y + uc * Dv) * sz;
        }
    }
}

// ---------------------------------------------------------------------------
// host launcher (graph-capturable: launches only)
// ---------------------------------------------------------------------------
extern "C" void kernel_launch(void* const* d_in, const int* in_sizes, int n_in,
                              void* d_out, int out_size) {
    const float* x       = (const float*)d_in[0];
    const float* W_in    = (const float*)d_in[1];
    const float* conv_k  = (const float*)d_in[2];
    const float* conv_b  = (const float*)d_in[3];
    const float* W_xproj = (const float*)d_in[4];
    const float* W_dt    = (const float*)d_in[5];
    const float* b_dt    = (const float*)d_in[6];
    const float* A_log   = (const float*)d_in[7];
    const float* Dp      = (const float*)d_in[8];
    const float* W_out   = (const float*)d_in[9];
    float* out = (float*)d_out;

    float *xz, *u, *xdbl, *dt, *ys, *pxd, *pout;
    cudaGetSymbolAddress((void**)&xz,   g_xz);
    cudaGetSymbolAddress((void**)&u,    g_u);
    cudaGetSymbolAddress((void**)&xdbl, g_xdbl);
    cudaGetSymbolAddress((void**)&dt,   g_dt);
    cudaGetSymbolAddress((void**)&ys,   g_ys);
    cudaGetSymbolAddress((void**)&pxd,  g_pxd);
    cudaGetSymbolAddress((void**)&pout, g_pout);

    // opt-in to 75.8KB dynamic smem (attribute set is not stream work; capture-safe)
    cudaFuncSetAttribute(tgemm2<0, 0>, cudaFuncAttributeMaxDynamicSharedMemorySize, TG_SMEM_BYTES);
    cudaFuncSetAttribute(tgemm2<1, 0>, cudaFuncAttributeMaxDynamicSharedMemorySize, TG_SMEM_BYTES);
    cudaFuncSetAttribute(tgemm2<0, 1>, cudaFuncAttributeMaxDynamicSharedMemorySize, TG_SMEM_BYTES);

    // 0) A = -exp(A_log)
    prep_kernel<<<(DI * NSTATE) / 256, 256>>>(A_log);

    // 1) in_proj: xz = x @ W_in           (2048 x 4096, K=1024) — tensor tf32
    tgemm2<0, 0><<<dim3(2 * DI / 128, NT / 128, 1), 256, TG_SMEM_BYTES>>>(
        x, W_in, xz, NT, 2 * DI, DM, DM, 2 * DI, 2 * DI,
        DM, 0, nullptr);

    // 2) depthwise conv + SiLU -> u
    conv_silu_kernel<<<(NT * DI) / 256, 256>>>(conv_k, conv_b);

    // 3) xdbl = u @ W_xproj               (2048 x 160, K=2048), split-K 8 — tensor
    tgemm2<0, 1><<<dim3(2, NT / 128, 8), 256, TG_SMEM_BYTES>>>(
        u, W_xproj, pxd, NT, XPN, DI, DI, XPN, XPN,
        DI / 8, (long long)NT * XPN, nullptr);
    reduce8_kernel<<<(NT * XPN) / 256, 256>>>();

    // 4) dt = softplus(xdbl[:, :128] @ W_dt + b_dt)   (2048 x 2048, K=128) — tensor
    tgemm2<1, 0><<<dim3(DI / 128, NT / 128, 1), 256, TG_SMEM_BYTES>>>(
        xdbl, W_dt, dt, NT, DI, DTR, XPN, DI, DI,
        DTR, 0, b_dt);

    // 5) selective scan (fused skip + gate) -> ys
    scan_kernel<<<dim3(DI / 32, 2), 256>>>(Dp);

    // 6) out = ys @ W_out                 (2048 x 1024, K=2048), split-K 2 — tensor
    tgemm2<0, 0><<<dim3(DM / 128, NT / 128, 2), 256, TG_SMEM_BYTES>>>(
        ys, W_out, pout, NT, DM, DI, DI, DM, DM,
        DI / 2, (long long)NT * DM, nullptr);
    reduce2_kernel<<<(NT * DM) / 256, 256>>>(out);
}